// round 17
// baseline (speedup 1.0000x reference)
#include <cuda_runtime.h>
#include <math.h>
#include <stdint.h>

#define BB 2
#define LL 2048
#define DD 1024
#define HH 16
#define DH 64
#define TK 32
#define SCALE 0.125f   // 1/sqrt(64)

// ---------------- scratch (device globals; no allocs allowed) ----------------
__device__ float g_q   [(size_t)BB*LL*DD];
__device__ float g_kv  [(size_t)BB*LL*2*DH];
__device__ float g_k   [(size_t)BB*LL*DH];
__device__ float g_v   [(size_t)BB*LL*DH];
__device__ float g_part[BB*16*128];
__device__ float g_sims[(size_t)BB*HH*LL*LL];       // 512 MB
__device__ float g_rowmax[BB*HH*LL];
__device__ float g_topv[(size_t)BB*HH*LL*TK];
__device__ int   g_topi[(size_t)BB*HH*LL*TK];
__device__ float g_attn[(size_t)BB*LL*DD];

// ordered-uint key helpers (monotone float <-> uint map)
__device__ __forceinline__ unsigned f2key(float x) {
    unsigned u = __float_as_uint(x);
    return u ^ ((unsigned)((int)u >> 31) | 0x80000000u);
}
__device__ __forceinline__ float key2f(unsigned k) {
    unsigned u = (k & 0x80000000u) ? (k ^ 0x80000000u) : ~k;
    return __uint_as_float(u);
}

// ---------------- packed f32x2 helpers (Blackwell 2x FP32 path) -------------
__device__ __forceinline__ void ffma2(unsigned long long &d,
                                      unsigned long long a, unsigned long long b) {
    asm("fma.rn.f32x2 %0, %1, %2, %0;" : "+l"(d) : "l"(a), "l"(b));
}
__device__ __forceinline__ unsigned long long pack2(float x) {
    unsigned long long r;
    asm("mov.b64 %0, {%1, %1};" : "=l"(r) : "r"(__float_as_uint(x)));
    return r;
}
__device__ __forceinline__ float fcomp(float4 v, int j) {
    return (j == 0) ? v.x : (j == 1) ? v.y : (j == 2) ? v.z : v.w;
}

// ---------------- fp32 GEMM body: C(MxN) = A(MxK) @ B(KxN) ----------------
// 128x128 tile, 256 threads; per-thread 4 rows x 16 cols (8 u64 col-pairs).
// B loaded ONCE per kk (4 x 1-cycle LDS.128), A 4xfloat4 per k4.
// Per-element accumulation stays kk-sequential ascending -> bitwise-stable.
__device__ __forceinline__ void sgemm_body(
    const float* __restrict__ A, const float* __restrict__ Bm,
    float* __restrict__ C, int Ndim, int Kdim, int brow, int bcol)
{
    __shared__ float As[128*36];   // [m][k] pad 36
    __shared__ float Bs[32*132];   // [k][n] pad 132
    int tid = threadIdx.x;
    int r0  = (tid >> 3) * 4;      // 0..124, 4 consecutive rows
    int c0  = (tid & 7) * 16;      // 0..112, 16 consecutive cols
    unsigned long long acc2[4][8];
#pragma unroll
    for (int i = 0; i < 4; i++)
#pragma unroll
        for (int j = 0; j < 8; j++) acc2[i][j] = 0ull;

    for (int kt = 0; kt < Kdim; kt += 32) {
#pragma unroll
        for (int i = 0; i < 4; i++) {
            int f4 = tid + i*256;
            int r = f4 >> 3, c4 = f4 & 7;
            float4 v = *(const float4*)(A + (size_t)(brow + r)*Kdim + kt + c4*4);
            *(float4*)&As[r*36 + c4*4] = v;
        }
#pragma unroll
        for (int i = 0; i < 4; i++) {
            int f4 = tid + i*256;
            int r = f4 >> 5, c4 = f4 & 31;
            *(float4*)&Bs[r*132 + c4*4] =
                *(const float4*)(Bm + (size_t)(kt + r)*Ndim + bcol + c4*4);
        }
        __syncthreads();
#pragma unroll
        for (int k4 = 0; k4 < 8; k4++) {
            float4 a4[4];
#pragma unroll
            for (int i = 0; i < 4; i++)
                a4[i] = *(float4*)&As[(r0 + i)*36 + k4*4];
#pragma unroll
            for (int j = 0; j < 4; j++) {
                int kk = k4*4 + j;
                ulonglong2 b0 = *(const ulonglong2*)&Bs[kk*132 + c0];
                ulonglong2 b1 = *(const ulonglong2*)&Bs[kk*132 + c0 + 4];
                ulonglong2 b2 = *(const ulonglong2*)&Bs[kk*132 + c0 + 8];
                ulonglong2 b3 = *(const ulonglong2*)&Bs[kk*132 + c0 + 12];
#pragma unroll
                for (int i = 0; i < 4; i++) {
                    unsigned long long ap = pack2(fcomp(a4[i], j));
                    ffma2(acc2[i][0], ap, b0.x);
                    ffma2(acc2[i][1], ap, b0.y);
                    ffma2(acc2[i][2], ap, b1.x);
                    ffma2(acc2[i][3], ap, b1.y);
                    ffma2(acc2[i][4], ap, b2.x);
                    ffma2(acc2[i][5], ap, b2.y);
                    ffma2(acc2[i][6], ap, b3.x);
                    ffma2(acc2[i][7], ap, b3.y);
                }
            }
        }
        __syncthreads();
    }
#pragma unroll
    for (int i = 0; i < 4; i++) {
        size_t r = (size_t)(brow + r0 + i)*Ndim + bcol + c0;
        *(ulonglong2*)(C + r)      = make_ulonglong2(acc2[i][0], acc2[i][1]);
        *(ulonglong2*)(C + r + 4)  = make_ulonglong2(acc2[i][2], acc2[i][3]);
        *(ulonglong2*)(C + r + 8)  = make_ulonglong2(acc2[i][4], acc2[i][5]);
        *(ulonglong2*)(C + r + 12) = make_ulonglong2(acc2[i][6], acc2[i][7]);
    }
}

// z=0: A0@B0 -> C0 (N0 cols). z=1: A1@B1 -> C1 (128 cols, blockIdx.x==0 only).
__global__ __launch_bounds__(256, 2) void sgemm2_kernel(
    const float* __restrict__ A0, const float* __restrict__ B0, float* __restrict__ C0,
    const float* __restrict__ A1, const float* __restrict__ B1, float* __restrict__ C1,
    int N0, int Kdim)
{
    if (blockIdx.z == 0) {
        sgemm_body(A0, B0, C0, N0, Kdim, blockIdx.y*128, blockIdx.x*128);
    } else {
        if (blockIdx.x != 0) return;
        sgemm_body(A1, B1, C1, 128, Kdim, blockIdx.y*128, 0);
    }
}

// ---------------- sequence-axis L2 norm of k,v columns ----------------
__global__ void colsq_kernel() {
    int b = blockIdx.x >> 4, chunk = blockIdx.x & 15;
    int j = threadIdx.x & 127, p = threadIdx.x >> 7;
    const float* base = g_kv + ((size_t)b*LL + chunk*128)*128;
    float ss = 0.f;
    for (int ll = p; ll < 128; ll += 2) {
        float v = base[ll*128 + j];
        ss += v*v;
    }
    __shared__ float sh[256];
    sh[threadIdx.x] = ss;
    __syncthreads();
    if (p == 0) g_part[(size_t)blockIdx.x*128 + j] = ss + sh[128 + j];
}

__global__ void normalize_kernel() {  // grid 2048, 256 thr
    int idx = blockIdx.x*256 + threadIdx.x;
    int j  = idx & 127;
    int bl = idx >> 7;
    int b  = bl >> 11;
    float s = 0.f;
#pragma unroll
    for (int c = 0; c < 16; c++) s += g_part[(b*16 + c)*128 + j];
    float n = sqrtf(s);
    n = fmaxf(n, 1e-12f);
    float v = g_kv[(size_t)idx] / n;
    if (j < 64) g_k[(size_t)bl*64 + j]        = v;
    else        g_v[(size_t)bl*64 + (j - 64)] = v;
}

// ---------------- sims = q @ k^T (f32x2, 4x16 micro, 2 CTAs/SM) -------------
// grid (mtile 16, ltile 16, z 32). 128x128 tile, K=64.
__global__ __launch_bounds__(256, 2) void sims_kernel() {
    extern __shared__ float sm[];
    float* Qs = sm;              // [128][68]
    float* Kt = sm + 128*68;     // [64][132]
    int z = blockIdx.z, b = z >> 4, h = z & 15;
    int lbase = blockIdx.y * 128, mbase = blockIdx.x * 128;
    const float* Aq = g_q + (size_t)b*LL*DD + h*DH;
    const float* Bk = g_k + (size_t)b*LL*DH;
    float* Cs = g_sims + (size_t)z*LL*LL;
    int tid = threadIdx.x;
#pragma unroll
    for (int i = 0; i < 8; i++) {            // Q tile 128x64
        int f4 = tid + i*256;
        int r = f4 >> 4, c4 = f4 & 15;
        float4 v = *(const float4*)(Aq + (size_t)(lbase + r)*DD + c4*4);
        *(float4*)&Qs[r*68 + c4*4] = v;
    }
#pragma unroll
    for (int i = 0; i < 8; i++) {            // K tile 128x64 -> transposed
        int f4 = tid + i*256;
        int lo = f4 & 31, hi = f4 >> 5;
        int r  = (lo & 7) + 8*(hi & 15);
        int c4 = (lo >> 3) + 4*(hi >> 4);
        float4 v = *(const float4*)(Bk + (size_t)(mbase + r)*DH + c4*4);
        Kt[(c4*4+0)*132 + r] = v.x; Kt[(c4*4+1)*132 + r] = v.y;
        Kt[(c4*4+2)*132 + r] = v.z; Kt[(c4*4+3)*132 + r] = v.w;
    }
    __syncthreads();
    int r0 = (tid >> 3) * 4;      // 4 consecutive l-rows
    int c0 = (tid & 7) * 16;      // 16 consecutive m-cols
    unsigned long long acc2[4][8];
#pragma unroll
    for (int i = 0; i < 4; i++)
#pragma unroll
        for (int j = 0; j < 8; j++) acc2[i][j] = 0ull;
#pragma unroll
    for (int k4 = 0; k4 < 16; k4++) {
        float4 a4[4];
#pragma unroll
        for (int i = 0; i < 4; i++)
            a4[i] = *(float4*)&Qs[(r0 + i)*68 + k4*4];
#pragma unroll
        for (int j = 0; j < 4; j++) {
            int kk = k4*4 + j;
            ulonglong2 b0 = *(const ulonglong2*)&Kt[kk*132 + c0];
            ulonglong2 b1 = *(const ulonglong2*)&Kt[kk*132 + c0 + 4];
            ulonglong2 b2 = *(const ulonglong2*)&Kt[kk*132 + c0 + 8];
            ulonglong2 b3 = *(const ulonglong2*)&Kt[kk*132 + c0 + 12];
#pragma unroll
            for (int i = 0; i < 4; i++) {
                unsigned long long ap = pack2(fcomp(a4[i], j));
                ffma2(acc2[i][0], ap, b0.x);
                ffma2(acc2[i][1], ap, b0.y);
                ffma2(acc2[i][2], ap, b1.x);
                ffma2(acc2[i][3], ap, b1.y);
                ffma2(acc2[i][4], ap, b2.x);
                ffma2(acc2[i][5], ap, b2.y);
                ffma2(acc2[i][6], ap, b3.x);
                ffma2(acc2[i][7], ap, b3.y);
            }
        }
    }
#pragma unroll
    for (int i = 0; i < 4; i++) {
        size_t off = (size_t)(lbase + r0 + i)*LL + mbase + c0;
        *(ulonglong2*)(Cs + off)      = make_ulonglong2(acc2[i][0], acc2[i][1]);
        *(ulonglong2*)(Cs + off + 4)  = make_ulonglong2(acc2[i][2], acc2[i][3]);
        *(ulonglong2*)(Cs + off + 8)  = make_ulonglong2(acc2[i][4], acc2[i][5]);
        *(ulonglong2*)(Cs + off + 12) = make_ulonglong2(acc2[i][6], acc2[i][7]);
    }
}

// ---------------- per-row: max + exact top-32 ----------------
__global__ __launch_bounds__(256) void stats_topk_kernel() {  // grid 65536
    __shared__ unsigned cand_key[256];
    __shared__ int      cand_idx[256];
    __shared__ unsigned redk[8];
    size_t row = blockIdx.x;
    const float* S = g_sims + row * LL;
    int tid = threadIdx.x, lane = tid & 31, wid = tid >> 5;

    float4 a = ((const float4*)S)[tid];
    float4 c = ((const float4*)S)[tid + 256];
    float v[8] = {a.x, a.y, a.z, a.w, c.x, c.y, c.z, c.w};
    unsigned key[8];
#pragma unroll
    for (int j = 0; j < 8; j++) key[j] = f2key(v[j]);

    unsigned km = key[0];
#pragma unroll
    for (int j = 1; j < 8; j++) km = max(km, key[j]);
    km = __reduce_max_sync(0xffffffffu, km);
    if (lane == 0) redk[wid] = km;
    __syncthreads();
    if (tid == 0) {
        unsigned m = redk[0];
        for (int w = 1; w < 8; w++) m = max(m, redk[w]);
        g_rowmax[row] = key2f(m);
    }

    unsigned lk = 0; int lj = 0;
#pragma unroll
    for (int j = 0; j < 8; j++) if (key[j] > lk) { lk = key[j]; lj = j; }
    for (int it = 0; it < TK; it++) {
        unsigned w = __reduce_max_sync(0xffffffffu, lk);
        unsigned ball = __ballot_sync(0xffffffffu, lk == w);
        int src = __ffs(ball) - 1;
        if (lane == src) {
            cand_key[wid*32 + it] = w;
            cand_idx[wid*32 + it] = (lj < 4) ? (4*tid + lj) : (1024 + 4*tid + lj - 4);
            key[lj] = 0u;
            lk = 0; lj = 0;
#pragma unroll
            for (int j = 0; j < 8; j++) if (key[j] > lk) { lk = key[j]; lj = j; }
        }
    }
    __syncthreads();

    if (wid == 0) {
        unsigned mkey[8]; int midx[8];
#pragma unroll
        for (int j = 0; j < 8; j++) {
            mkey[j] = cand_key[lane*8 + j];
            midx[j] = cand_idx[lane*8 + j];
        }
        unsigned mk = 0; int mj = 0;
#pragma unroll
        for (int j = 0; j < 8; j++) if (mkey[j] > mk) { mk = mkey[j]; mj = j; }
        for (int it = 0; it < TK; it++) {
            unsigned w = __reduce_max_sync(0xffffffffu, mk);
            unsigned ball = __ballot_sync(0xffffffffu, mk == w);
            int src = __ffs(ball) - 1;
            if (lane == src) {
                g_topv[row*TK + it] = key2f(w);
                g_topi[row*TK + it] = midx[mj];
                mkey[mj] = 0u;
                mk = 0; mj = 0;
#pragma unroll
                for (int j = 0; j < 8; j++) if (mkey[j] > mk) { mk = mkey[j]; mj = j; }
            }
        }
    }
}

// ---------------- local = (sum_m e_m v_m)/(sum_m e_m), packed f32x2 ---------
__global__ __launch_bounds__(256, 2) void pv_kernel() {
    extern __shared__ float sm[];
    float* Pt   = sm;                 // [64][260]
    float* Vs   = sm + 64*260;        // [64][68]
    float* smx  = Vs + 64*68;         // [256]
    float* part = smx + 256;          // [4][256]
    float* rsin = part + 1024;        // [256]
    int z = blockIdx.y, b = z >> 4, h = z & 15;
    int lbase = blockIdx.x * 256;
    const float* S = g_sims + (size_t)z*LL*LL;
    int tid = threadIdx.x;
    smx[tid] = g_rowmax[(size_t)z*LL + lbase + tid];
    __syncthreads();
    int rowg4 = (tid >> 4)*4;
    int c0    = (tid & 15)*4;
    unsigned long long acc2[8][4];
#pragma unroll
    for (int i = 0; i < 8; i++)
#pragma unroll
        for (int j = 0; j < 4; j++) acc2[i][j] = 0ull;
    float psum[4] = {0.f, 0.f, 0.f, 0.f};

    for (int mt = 0; mt < LL; mt += 64) {
#pragma unroll
        for (int i = 0; i < 16; i++) {
            int f4 = tid + i*256;
            int r  = (f4 & 7) + 8*((f4 >> 5) & 31);
            int c4 = ((f4 >> 3) & 3) + 4*(f4 >> 10);
            float4 v = *(const float4*)(S + (size_t)(lbase + r)*LL + mt + c4*4);
            float m = smx[r];
            float e0 = __expf((v.x - m)*SCALE);
            float e1 = __expf((v.y - m)*SCALE);
            float e2 = __expf((v.z - m)*SCALE);
            float e3 = __expf((v.w - m)*SCALE);
            Pt[(c4*4+0)*260 + r] = e0;
            Pt[(c4*4+1)*260 + r] = e1;
            Pt[(c4*4+2)*260 + r] = e2;
            Pt[(c4*4+3)*260 + r] = e3;
            psum[i & 3] += (e0 + e1) + (e2 + e3);
        }
#pragma unroll
        for (int i = 0; i < 4; i++) {
            int f4 = tid + i*256;
            int r = f4 >> 4, c4 = f4 & 15;
            *(float4*)&Vs[r*68 + c4*4] =
                *(const float4*)(g_v + ((size_t)b*LL + mt + r)*DH + c4*4);
        }
        __syncthreads();
#pragma unroll 8
        for (int ml = 0; ml < 64; ml++) {
            ulonglong2 a0 = *(const ulonglong2*)&Pt[ml*260 + rowg4];
            ulonglong2 a1 = *(const ulonglong2*)&Pt[ml*260 + 64  + rowg4];
            ulonglong2 a2 = *(const ulonglong2*)&Pt[ml*260 + 128 + rowg4];
            ulonglong2 a3 = *(const ulonglong2*)&Pt[ml*260 + 192 + rowg4];
            float4 bv = *(float4*)&Vs[ml*68 + c0];
            unsigned long long bp0 = pack2(bv.x), bp1 = pack2(bv.y);
            unsigned long long bp2 = pack2(bv.z), bp3 = pack2(bv.w);
            unsigned long long ap[8] = {a0.x, a0.y, a1.x, a1.y,
                                        a2.x, a2.y, a3.x, a3.y};
#pragma unroll
            for (int i = 0; i < 8; i++) {
                ffma2(acc2[i][0], ap[i], bp0);
                ffma2(acc2[i][1], ap[i], bp1);
                ffma2(acc2[i][2], ap[i], bp2);
                ffma2(acc2[i][3], ap[i], bp3);
            }
        }
        __syncthreads();
    }

#pragma unroll
    for (int ii = 0; ii < 4; ii++) part[ii*256 + tid] = psum[ii];
    __syncthreads();
    {
        int rho = tid;
        int ii  = rho >> 6;
        float s = 0.f;
#pragma unroll
        for (int k = 0; k < 4; k++) {
            int t = (rho & 7) | (k << 3) | (((rho >> 3) & 7) << 5);
            s += part[ii*256 + t];
        }
        rsin[rho] = 1.0f / s;
    }
    __syncthreads();

#pragma unroll
    for (int q = 0; q < 4; q++)
#pragma unroll
        for (int p = 0; p < 2; p++) {
            float lo0, hi0, lo1, hi1, lo2, hi2, lo3, hi3;
            asm("mov.b64 {%0, %1}, %2;" : "=f"(lo0), "=f"(hi0) : "l"(acc2[q*2+p][0]));
            asm("mov.b64 {%0, %1}, %2;" : "=f"(lo1), "=f"(hi1) : "l"(acc2[q*2+p][1]));
            asm("mov.b64 {%0, %1}, %2;" : "=f"(lo2), "=f"(hi2) : "l"(acc2[q*2+p][2]));
            asm("mov.b64 {%0, %1}, %2;" : "=f"(lo3), "=f"(hi3) : "l"(acc2[q*2+p][3]));
            int rl0 = q*64 + rowg4 + 2*p;
            float iv0 = rsin[rl0], iv1 = rsin[rl0 + 1];
            *(float4*)(g_attn + ((size_t)b*LL + lbase + rl0)*DD + h*DH + c0) =
                make_float4(lo0*iv0, lo1*iv0, lo2*iv0, lo3*iv0);
            *(float4*)(g_attn + ((size_t)b*LL + lbase + rl0 + 1)*DD + h*DH + c0) =
                make_float4(hi0*iv1, hi1*iv1, hi2*iv1, hi3*iv1);
        }
}

// ---------------- retrieved = softmax(topv*scale) @ k[topi] ----------------
__global__ __launch_bounds__(256) void retrieved_kernel() {
    __shared__ float ps[8][32];
    __shared__ int   tis[8][32];
    int wid = threadIdx.x >> 5, lane = threadIdx.x & 31;
    size_t row = (size_t)blockIdx.x*8 + wid;
    int z = (int)(row >> 11), l = (int)(row & 2047);
    int b = z >> 4, h = z & 15;
    float tv = g_topv[row*TK + lane];
    int   ti = g_topi[row*TK + lane];
    float mx = __shfl_sync(0xffffffffu, tv, 0);
    float p = __expf((tv - mx)*SCALE);
    float psum = p;
#pragma unroll
    for (int o = 16; o; o >>= 1) psum += __shfl_xor_sync(0xffffffffu, psum, o);
    ps[wid][lane] = p / psum;
    tis[wid][lane] = ti;
    __syncwarp();
    const float* kb = g_k + (size_t)b*LL*DH;
    float a0 = 0.f, a1 = 0.f;
#pragma unroll 8
    for (int t = 0; t < TK; t++) {
        float w = ps[wid][t];
        const float* kr = kb + (size_t)tis[wid][t]*DH;
        a0 += w * kr[lane];
        a1 += w * kr[lane + 32];
    }
    size_t off = ((size_t)b*LL + l)*DD + h*DH;
    g_attn[off + lane]      += a0;
    g_attn[off + lane + 32] += a1;
}

// ---------------- launch ----------------
extern "C" void kernel_launch(void* const* d_in, const int* in_sizes, int n_in,
                              void* d_out, int out_size)
{
    const float* q_in     = (const float*)d_in[0];
    const float* kv_in    = (const float*)d_in[1];
    const float* w_q      = (const float*)d_in[2];
    const float* w_kv     = (const float*)d_in[3];
    const float* w_concat = (const float*)d_in[4];
    float* out = (float*)d_out;

    float *p_q, *p_kv, *p_attn;
    cudaGetSymbolAddress((void**)&p_q,    g_q);
    cudaGetSymbolAddress((void**)&p_kv,   g_kv);
    cudaGetSymbolAddress((void**)&p_attn, g_attn);

    static const int SIMS_SMEM = (128*68 + 64*132)*4;                     // 68608
    static const int PV_SMEM   = (64*260 + 64*68 + 256 + 1024 + 256)*4;   // 90112
    cudaFuncSetAttribute(sims_kernel, cudaFuncAttributeMaxDynamicSharedMemorySize, SIMS_SMEM);
    cudaFuncSetAttribute(pv_kernel,   cudaFuncAttributeMaxDynamicSharedMemorySize, PV_SMEM);

    // 1. q = q_in @ w_q (z=0) and kv = kv_in @ w_kv (z=1), one launch
    sgemm2_kernel<<<dim3(8, 32, 2), 256>>>(q_in, w_q, p_q, kv_in, w_kv, p_kv, DD, DD);
    // 2-3. l2 norm over sequence axis
    colsq_kernel<<<32, 256>>>();
    normalize_kernel<<<2048, 256>>>();
    // 4. sims (f32x2, 4x16 micro, 2 CTAs/SM) — ncu capture slot
    sims_kernel<<<dim3(16, 16, 32), 256, SIMS_SMEM>>>();
    // 5. row max + exact top-32
    stats_topk_kernel<<<BB*HH*LL, 256>>>();
    // 6. local attention (flash-normalized P@V, f32x2) -> g_attn
    pv_kernel<<<dim3(8, 32), 256, PV_SMEM>>>();
    // 7. retrieved (+= into g_attn)
    retrieved_kernel<<<BB*HH*LL/8, 256>>>();
    // 8. out = attn @ w_concat
    sgemm2_kernel<<<dim3(8, 32, 1), 256>>>(p_attn, w_concat, out, p_attn, w_concat, out, DD, DD);
}